// round 1
// baseline (speedup 1.0000x reference)
#include <cuda_runtime.h>

// Problem constants
#define S   1048576          // 1024*1024
#define S4  (S / 4)          // float4 chunks per slab
#define TPB 256
#define NBLK_A (S4 / TPB)    // 1024 blocks, each thread handles one 4-s chunk
#define NCOMP 30             // 3 (V0) + 9 (V1) + 9 (V2) + 9 (V3)

// Deterministic scratch (no device allocation allowed)
__device__ float g_bpart[NBLK_A * NCOMP];
__device__ float g_f[3];

// ---------------------------------------------------------------------------
// Kernel A: V_k[r,q] = sum_s z[s] * TT_k[r,s,q]  (partial per block)
// Layout of acc / g_bpart components:
//   [0..2]   = V0[0][q]
//   [3..11]  = V1[r*3+q]
//   [12..20] = V2[r*3+q]
//   [21..29] = V3[r*3+q]
// ---------------------------------------------------------------------------
__device__ __forceinline__ void slab_accum(const float4* __restrict__ p,
                                           const float zz[4], float* a) {
    // 12 consecutive floats = 4 s-values x 3 q-values, element e -> (s=e/3, q=e%3)
    float4 v0 = p[0];
    float4 v1 = p[1];
    float4 v2 = p[2];
    a[0] += zz[0] * v0.x;  a[1] += zz[0] * v0.y;  a[2] += zz[0] * v0.z;
    a[0] += zz[1] * v0.w;  a[1] += zz[1] * v1.x;  a[2] += zz[1] * v1.y;
    a[0] += zz[2] * v1.z;  a[1] += zz[2] * v1.w;  a[2] += zz[2] * v2.x;
    a[0] += zz[3] * v2.y;  a[1] += zz[3] * v2.z;  a[2] += zz[3] * v2.w;
}

__global__ void __launch_bounds__(TPB)
reduce_k(const float* __restrict__ z,
         const float* __restrict__ t0,
         const float* __restrict__ t1,
         const float* __restrict__ t2,
         const float* __restrict__ t3) {
    const int idx = blockIdx.x * TPB + threadIdx.x;   // 0 .. S4-1

    float acc[NCOMP];
#pragma unroll
    for (int i = 0; i < NCOMP; i++) acc[i] = 0.0f;

    float4 zv = reinterpret_cast<const float4*>(z)[idx];
    float zz[4] = {zv.x, zv.y, zv.z, zv.w};

    const int slabStride4 = 3 * S / 4;   // float4 stride between r-slabs of a (*,S,3) core
    const int base4 = idx * 3;           // float4 offset within a slab

    // TT0: (1, S, 3)
    slab_accum(reinterpret_cast<const float4*>(t0) + base4, zz, acc + 0);

    // TT1..TT3: (3, S, 3)
#pragma unroll
    for (int r = 0; r < 3; r++)
        slab_accum(reinterpret_cast<const float4*>(t1) + r * slabStride4 + base4, zz, acc + 3 + r * 3);
#pragma unroll
    for (int r = 0; r < 3; r++)
        slab_accum(reinterpret_cast<const float4*>(t2) + r * slabStride4 + base4, zz, acc + 12 + r * 3);
#pragma unroll
    for (int r = 0; r < 3; r++)
        slab_accum(reinterpret_cast<const float4*>(t3) + r * slabStride4 + base4, zz, acc + 21 + r * 3);

    // Warp reduction of all 30 components
    const unsigned FULL = 0xffffffffu;
#pragma unroll
    for (int i = 0; i < NCOMP; i++) {
        float v = acc[i];
        v += __shfl_down_sync(FULL, v, 16);
        v += __shfl_down_sync(FULL, v, 8);
        v += __shfl_down_sync(FULL, v, 4);
        v += __shfl_down_sync(FULL, v, 2);
        v += __shfl_down_sync(FULL, v, 1);
        acc[i] = v;
    }

    __shared__ float sred[TPB / 32][NCOMP];
    const int warp = threadIdx.x >> 5;
    const int lane = threadIdx.x & 31;
    if (lane == 0) {
#pragma unroll
        for (int i = 0; i < NCOMP; i++) sred[warp][i] = acc[i];
    }
    __syncthreads();

    if (threadIdx.x < NCOMP) {
        float s = 0.0f;
#pragma unroll
        for (int w = 0; w < TPB / 32; w++) s += sred[w][threadIdx.x];
        g_bpart[blockIdx.x * NCOMP + threadIdx.x] = s;   // deterministic: no atomics
    }
}

// ---------------------------------------------------------------------------
// Kernel B: reduce block partials -> V matrices, then f = V0 @ V1 @ V2 @ V3
// 30 warps: warp w reduces component w over NBLK_A partials.
// ---------------------------------------------------------------------------
__global__ void __launch_bounds__(NCOMP * 32)
finalize_k() {
    const int comp = threadIdx.x >> 5;   // 0..29
    const int lane = threadIdx.x & 31;

    float s = 0.0f;
    for (int b = lane; b < NBLK_A; b += 32)
        s += g_bpart[b * NCOMP + comp];

    const unsigned FULL = 0xffffffffu;
    s += __shfl_down_sync(FULL, s, 16);
    s += __shfl_down_sync(FULL, s, 8);
    s += __shfl_down_sync(FULL, s, 4);
    s += __shfl_down_sync(FULL, s, 2);
    s += __shfl_down_sync(FULL, s, 1);

    __shared__ float V[NCOMP];
    if (lane == 0) V[comp] = s;
    __syncthreads();

    if (threadIdx.x == 0) {
        float f0 = V[0], f1 = V[1], f2 = V[2];       // V0 : (1,3)
#pragma unroll
        for (int c = 0; c < 3; c++) {                // chain with V1,V2,V3 (3x3, row-major [r*3+q])
            const float* M = V + 3 + c * 9;
            float g0 = f0 * M[0] + f1 * M[3] + f2 * M[6];
            float g1 = f0 * M[1] + f1 * M[4] + f2 * M[7];
            float g2 = f0 * M[2] + f1 * M[5] + f2 * M[8];
            f0 = g0; f1 = g1; f2 = g2;
        }
        g_f[0] = f0; g_f[1] = f1; g_f[2] = f2;
    }
}

// ---------------------------------------------------------------------------
// Kernel C: out[s] = f0*TT4[0,s,0] + f1*TT4[1,s,0] + f2*TT4[2,s,0]
// TT4 is (3, S, 1) -> slab r at offset r*S floats.
// ---------------------------------------------------------------------------
__global__ void __launch_bounds__(TPB)
bcast_k(const float* __restrict__ t4, float* __restrict__ out) {
    const int idx = blockIdx.x * TPB + threadIdx.x;   // 0 .. S4-1
    const float f0 = g_f[0];
    const float f1 = g_f[1];
    const float f2 = g_f[2];

    const float4* p = reinterpret_cast<const float4*>(t4);
    float4 a = p[idx];
    float4 b = p[S4 + idx];
    float4 c = p[2 * S4 + idx];

    float4 o;
    o.x = f0 * a.x + f1 * b.x + f2 * c.x;
    o.y = f0 * a.y + f1 * b.y + f2 * c.y;
    o.z = f0 * a.z + f1 * b.z + f2 * c.z;
    o.w = f0 * a.w + f1 * b.w + f2 * c.w;
    reinterpret_cast<float4*>(out)[idx] = o;
}

// ---------------------------------------------------------------------------
extern "C" void kernel_launch(void* const* d_in, const int* in_sizes, int n_in,
                              void* d_out, int out_size) {
    const float* z  = (const float*)d_in[0];
    const float* t0 = (const float*)d_in[1];
    const float* t1 = (const float*)d_in[2];
    const float* t2 = (const float*)d_in[3];
    const float* t3 = (const float*)d_in[4];
    const float* t4 = (const float*)d_in[5];
    float* out = (float*)d_out;

    reduce_k<<<NBLK_A, TPB>>>(z, t0, t1, t2, t3);
    finalize_k<<<1, NCOMP * 32>>>();
    bcast_k<<<NBLK_A, TPB>>>(t4, out);
}

// round 3
// speedup vs baseline: 1.1309x; 1.1309x over previous
#include <cuda_runtime.h>

// Problem constants
#define S      1048576        // 1024*1024
#define S4     (S / 4)        // float4 chunks per slab (262144)
#define TPB    256
#define NSLAB  10             // TT0:r0, TT1:r0..2, TT2:r0..2, TT3:r0..2
#define PBLK   128            // blocks per slab
#define NITER  (S4 / (PBLK * TPB))   // 8 grid-stride iterations per thread
#define NCOMP  30             // 10 slabs x 3 q-components

// Deterministic scratch (no device allocation allowed)
// Layout: g_bpart[comp][PBLK]  -> contiguous per component for coalesced finalize
__device__ float g_bpart[NCOMP * PBLK];
__device__ float g_f[3];

// ---------------------------------------------------------------------------
// Kernel A: per-slab partial reduction.
//   slab = blockIdx.x % NSLAB   (so same-s-range blocks across slabs run
//                                concurrently -> z dedups in L2)
//   blk  = blockIdx.x / NSLAB
// Each thread accumulates 3 components (q=0,1,2) over NITER 4-s chunks.
// comp index = slab*3 + q  (matches old layout: V0->0..2, V1[r]->3+3r.., etc.)
// ---------------------------------------------------------------------------
__global__ void __launch_bounds__(TPB)
reduce_k(const float* __restrict__ z,
         const float* __restrict__ t0,
         const float* __restrict__ t1,
         const float* __restrict__ t2,
         const float* __restrict__ t3) {
    const int slab = blockIdx.x % NSLAB;
    const int blk  = blockIdx.x / NSLAB;

    // Resolve slab base pointer (static if-chain; no indexed array -> no spills)
    const float* base;
    {
        const int r = (slab == 0) ? 0 : ((slab - 1) % 3);
        const float* t = (slab == 0) ? t0 : (slab <= 3 ? t1 : (slab <= 6 ? t2 : t3));
        base = t + (size_t)r * (3u * S);
    }
    const float4* bp = reinterpret_cast<const float4*>(base);
    const float4* zp = reinterpret_cast<const float4*>(z);

    float a0 = 0.0f, a1 = 0.0f, a2 = 0.0f;

    int c = blk * TPB + threadIdx.x;               // chunk index, stride PBLK*TPB
#pragma unroll
    for (int it = 0; it < NITER; it++, c += PBLK * TPB) {
        float4 zv = zp[c];
        const float4* p = bp + (size_t)c * 3;
        float4 v0 = p[0];
        float4 v1 = p[1];
        float4 v2 = p[2];
        // 12 consecutive floats = 4 s x 3 q ; elem e -> (s=e/3, q=e%3)
        a0 += zv.x * v0.x;  a1 += zv.x * v0.y;  a2 += zv.x * v0.z;
        a0 += zv.y * v0.w;  a1 += zv.y * v1.x;  a2 += zv.y * v1.y;
        a0 += zv.z * v1.z;  a1 += zv.z * v1.w;  a2 += zv.z * v2.x;
        a0 += zv.w * v2.y;  a1 += zv.w * v2.z;  a2 += zv.w * v2.w;
    }

    // Warp reduction of 3 components
    const unsigned FULL = 0xffffffffu;
#pragma unroll
    for (int off = 16; off >= 1; off >>= 1) {
        a0 += __shfl_down_sync(FULL, a0, off);
        a1 += __shfl_down_sync(FULL, a1, off);
        a2 += __shfl_down_sync(FULL, a2, off);
    }

    __shared__ float sred[TPB / 32][3];
    const int warp = threadIdx.x >> 5;
    const int lane = threadIdx.x & 31;
    if (lane == 0) { sred[warp][0] = a0; sred[warp][1] = a1; sred[warp][2] = a2; }
    __syncthreads();

    if (threadIdx.x < 3) {
        float s = 0.0f;
#pragma unroll
        for (int w = 0; w < TPB / 32; w++) s += sred[w][threadIdx.x];
        g_bpart[(slab * 3 + threadIdx.x) * PBLK + blk] = s;   // deterministic
    }
}

// ---------------------------------------------------------------------------
// Kernel B: reduce block partials -> V (30 values), then f = V0 @ V1 @ V2 @ V3
// 30 warps, warp w reduces component w (its 128 partials are contiguous).
// ---------------------------------------------------------------------------
__global__ void __launch_bounds__(NCOMP * 32)
finalize_k() {
    const int comp = threadIdx.x >> 5;   // 0..29
    const int lane = threadIdx.x & 31;

    const float4* p = reinterpret_cast<const float4*>(g_bpart + comp * PBLK);
    float4 v = p[lane];                  // 32 lanes x 4 = 128 partials, coalesced
    float s = v.x + v.y + v.z + v.w;

    const unsigned FULL = 0xffffffffu;
#pragma unroll
    for (int off = 16; off >= 1; off >>= 1) s += __shfl_down_sync(FULL, s, off);

    __shared__ float V[NCOMP];
    if (lane == 0) V[comp] = s;
    __syncthreads();

    if (threadIdx.x == 0) {
        float f0 = V[0], f1 = V[1], f2 = V[2];       // V0 : (1,3)
#pragma unroll
        for (int c = 0; c < 3; c++) {                // V1,V2,V3 (3x3 row-major [r*3+q])
            const float* M = V + 3 + c * 9;
            float g0 = f0 * M[0] + f1 * M[3] + f2 * M[6];
            float g1 = f0 * M[1] + f1 * M[4] + f2 * M[7];
            float g2 = f0 * M[2] + f1 * M[5] + f2 * M[8];
            f0 = g0; f1 = g1; f2 = g2;
        }
        g_f[0] = f0; g_f[1] = f1; g_f[2] = f2;
    }
}

// ---------------------------------------------------------------------------
// Kernel C: out[s] = f0*TT4[0,s,0] + f1*TT4[1,s,0] + f2*TT4[2,s,0]
// ---------------------------------------------------------------------------
__global__ void __launch_bounds__(TPB)
bcast_k(const float* __restrict__ t4, float* __restrict__ out) {
    const int idx = blockIdx.x * TPB + threadIdx.x;   // 0 .. S4-1
    const float f0 = g_f[0];
    const float f1 = g_f[1];
    const float f2 = g_f[2];

    const float4* p = reinterpret_cast<const float4*>(t4);
    float4 a = p[idx];
    float4 b = p[S4 + idx];
    float4 c = p[2 * S4 + idx];

    float4 o;
    o.x = f0 * a.x + f1 * b.x + f2 * c.x;
    o.y = f0 * a.y + f1 * b.y + f2 * c.y;
    o.z = f0 * a.z + f1 * b.z + f2 * c.z;
    o.w = f0 * a.w + f1 * b.w + f2 * c.w;
    reinterpret_cast<float4*>(out)[idx] = o;
}

// ---------------------------------------------------------------------------
extern "C" void kernel_launch(void* const* d_in, const int* in_sizes, int n_in,
                              void* d_out, int out_size) {
    const float* z  = (const float*)d_in[0];
    const float* t0 = (const float*)d_in[1];
    const float* t1 = (const float*)d_in[2];
    const float* t2 = (const float*)d_in[3];
    const float* t3 = (const float*)d_in[4];
    const float* t4 = (const float*)d_in[5];
    float* out = (float*)d_out;

    reduce_k<<<NSLAB * PBLK, TPB>>>(z, t0, t1, t2, t3);
    finalize_k<<<1, NCOMP * 32>>>();
    bcast_k<<<S4 / TPB, TPB>>>(t4, out);
}